// round 10
// baseline (speedup 1.0000x reference)
#include <cuda_runtime.h>
#include <cuda_fp16.h>
#include <math.h>

#define LMAX 524288
#define NBS  592          // step grid (4 blocks x 148 SMs)
#define NTB  128          // step block
#define NBC  592          // convert grid
#define NTC  256          // convert block
#define ESHIFT 4.0f

// fp16 copy of z_past: [L][32] halves (16B-aligned for int4 access)
__device__ __align__(16) __half g_zh[(size_t)LMAX * 32];
// per-block partials: [block][132]  (c<4: s_h, c=4+h*32+i: S_h[i])
__device__ float  g_part[NBS * 132];
__device__ float  g_z[32];
__device__ float  g_uf[4][32];     // fp32 u (for epilogue correction)
__device__ __half2 g_uh[4][16];    // half2 u (for mainloop scores)
__device__ float  g_f[4][64];      // correction factors for rows l<64
__device__ unsigned int g_cnt = 0;

__device__ __forceinline__ __half2 h2shfl_xor(__half2 v, int o) {
    unsigned u = *(unsigned*)&v;
    u = __shfl_xor_sync(0xffffffffu, u, o);
    return *(__half2*)&u;
}

// ---- shared epilogue math: from smem sq (=0.5*q) compute u (g_uf/g_uh) and f (g_f)
__device__ __forceinline__ void compute_u_f(const float* sq, float (*su)[32],
                                            const float* k_w, const float* rbias,
                                            int off, int tid, int nthreads)
{
    if (tid < 128) {
        int h = tid >> 5, i = tid & 31;
        float u = 0.f;
#pragma unroll
        for (int j = 0; j < 8; j++) u += sq[8*h + j] * k_w[(8*h + j) * 32 + i];
        g_uf[h][i] = u;
        su[h][i] = u;
    }
    __syncthreads();
    if (tid < 64) {
        int h = tid >> 4, m = tid & 15;
        g_uh[h][m] = __floats2half2_rn(su[h][2*m], su[h][2*m+1]);
    }
    for (int task = tid; task < 256; task += nthreads) {
        int h = task >> 6, l = task & 63;
        int idx = off + l;
        idx = idx < 0 ? 0 : (idx > 128 ? 128 : idx);
        float d = 0.f;
#pragma unroll
        for (int j = 0; j < 8; j++)
            d += sq[8*h + j] * (rbias[idx * 32 + 8*h + j] - rbias[128 * 32 + 8*h + j]);
        g_f[h][l] = __expf(d);
    }
}

// ---------------- convert: z_past -> fp16, plus step-0 init (block 0) -------
__global__ __launch_bounds__(NTC)
void k_convert(const float* __restrict__ zp, int L,
               const float* __restrict__ cand,
               const float* __restrict__ q_w, const float* __restrict__ q_b,
               const float* __restrict__ k_w, const float* __restrict__ rbias,
               const int* __restrict__ pos)
{
    if (blockIdx.x == 0) {
        __shared__ float scand[32], sq[32], su[4][32];
        int tid = threadIdx.x;
        if (tid < 32) { scand[tid] = cand[tid]; g_z[tid] = cand[tid]; }
        __syncthreads();
        if (tid < 32) {
            float qq = q_b[tid];
#pragma unroll
            for (int i = 0; i < 32; i++) qq += scand[i] * q_w[tid * 32 + i];
            sq[tid] = 0.5f * qq;
        }
        __syncthreads();
        compute_u_f(sq, su, k_w, rbias, pos[0] - L + 64, tid, NTC);
        __syncthreads();
    }
    const int stride = gridDim.x * blockDim.x;
    for (int l = blockIdx.x * blockDim.x + threadIdx.x; l < L; l += stride) {
        const float4* row = (const float4*)(zp + (size_t)l * 32);
        __half2 h[16];
#pragma unroll
        for (int c = 0; c < 8; c++) {
            float4 t = row[c];
            h[2*c]   = __floats2half2_rn(t.x, t.y);
            h[2*c+1] = __floats2half2_rn(t.z, t.w);
        }
        int4* dst = (int4*)(g_zh + (size_t)l * 32);
        const int4* src = (const int4*)h;
#pragma unroll
        for (int c = 0; c < 4; c++) dst[c] = src[c];
    }
}

// ---------------- fused step: streaming + last-block epilogue ---------------
__global__ __launch_bounds__(NTB, 4)
void k_step(int L,
            const float* __restrict__ k_w,
            const float* __restrict__ v_w, const float* __restrict__ v_b,
            const float* __restrict__ o_w, const float* __restrict__ o_b,
            const float* __restrict__ q_w, const float* __restrict__ q_b,
            const float* __restrict__ rbias,
            const float* __restrict__ coupling,
            const float* __restrict__ norm_scale,
            const int* __restrict__ pos,
            float* __restrict__ outp, int last)
{
    const int tid  = threadIdx.x;
    const int gtid = blockIdx.x * NTB + tid;
    const int par  = gtid & 1;          // lane parity: which 16 components
    const int lane = tid & 31;

    __half2 uh[4][8];
#pragma unroll
    for (int h = 0; h < 4; h++)
#pragma unroll
        for (int m = 0; m < 8; m++) uh[h][m] = g_uh[h][par * 8 + m];

    float s[4] = {0.f, 0.f, 0.f, 0.f};
    __half2 sacc[4][8];
#pragma unroll
    for (int h = 0; h < 4; h++)
#pragma unroll
        for (int m = 0; m < 8; m++) sacc[h][m] = __floats2half2_rn(0.f, 0.f);

    const int rs = (NBS * NTB) >> 1;
    int r = gtid >> 1;
    int4 cv0, cv1;
    if (r < L) {
        const int4* zp = (const int4*)(g_zh + (size_t)r * 32 + par * 16);
        cv0 = zp[0]; cv1 = zp[1];
    }
    while (r < L) {
        int rn = r + rs;
        int4 nv0, nv1;
        if (rn < L) {
            const int4* zp = (const int4*)(g_zh + (size_t)rn * 32 + par * 16);
            nv0 = zp[0]; nv1 = zp[1];
        }
        __half2 zh[8];
        *(int4*)(&zh[0]) = cv0;
        *(int4*)(&zh[4]) = cv1;

        float e[4];
#pragma unroll
        for (int h = 0; h < 4; h++) {
            __half2 p = __hmul2(zh[0], uh[h][0]);
#pragma unroll
            for (int m = 1; m < 8; m++) p = __hfma2(zh[m], uh[h][m], p);
            float2 pf = __half22float2(p);
            float sc = pf.x + pf.y;
            sc += __shfl_xor_sync(0xffffffffu, sc, 1);
            e[h] = __expf(sc - ESHIFT);   // uniform shift cancels in S/s
            s[h] += e[h];
        }
#pragma unroll
        for (int h = 0; h < 4; h++) {
            __half2 eh = __float2half2_rn(e[h]);
#pragma unroll
            for (int m = 0; m < 8; m++)
                sacc[h][m] = __hfma2(eh, zh[m], sacc[h][m]);
        }
        cv0 = nv0; cv1 = nv1; r = rn;
    }

    // warp reduction among same-parity lanes (offsets 2,4,8,16)
#pragma unroll
    for (int o = 2; o <= 16; o <<= 1) {
#pragma unroll
        for (int h = 0; h < 4; h++) {
            s[h] += __shfl_xor_sync(0xffffffffu, s[h], o);
#pragma unroll
            for (int m = 0; m < 8; m++)
                sacc[h][m] = __hadd2(sacc[h][m], h2shfl_xor(sacc[h][m], o));
        }
    }

    __shared__ float sm_s[4][4];        // parity-0 only (parities are equal)
    __shared__ float sm_S[4][4][32];
    int w = tid >> 5;
    if (lane < 2) {
#pragma unroll
        for (int h = 0; h < 4; h++) {
            if (par == 0) sm_s[w][h] = s[h];
#pragma unroll
            for (int m = 0; m < 8; m++) {
                float2 f = __half22float2(sacc[h][m]);
                sm_S[w][h][par * 16 + 2*m]     = f.x;
                sm_S[w][h][par * 16 + 2*m + 1] = f.y;
            }
        }
    }
    __syncthreads();
    for (int c = tid; c < 132; c += NTB) {          // all 132 cells covered
        float r2;
        if (c < 4) {
            r2 = sm_s[0][c] + sm_s[1][c] + sm_s[2][c] + sm_s[3][c];
        } else {
            int h = (c - 4) >> 5, i = (c - 4) & 31;
            r2 = sm_S[0][h][i] + sm_S[1][h][i] + sm_S[2][h][i] + sm_S[3][h][i];
        }
        g_part[blockIdx.x * 132 + c] = r2;
    }

    // ---- last-block epilogue ----
    __shared__ bool amLast;
    __threadfence();
    if (tid == 0) {
        unsigned int v = atomicAdd(&g_cnt, 1u);
        amLast = (v == (unsigned int)(gridDim.x - 1));
    }
    __syncthreads();
    if (!amLast) return;

    __shared__ float red[132];
    for (int c = tid; c < 132; c += NTB) {
        float rr = 0.f;
        const float* pp = g_part + c;
#pragma unroll 4
        for (int b = 0; b < NBS; b++) rr += pp[b * 132];
        red[c] = rr;
    }
    // load first 64 rows of z (rel-bias correction region)
    __shared__ __align__(16) __half szh[64 * 32];
    for (int t = tid; t < 256; t += NTB)
        ((int4*)szh)[t] = ((const int4*)g_zh)[t];
    __shared__ float sw[4][64];
    __syncthreads();

    for (int task = tid; task < 256; task += NTB) {
        int h = task >> 6, l = task & 63;
        float sc = 0.f;
#pragma unroll
        for (int i = 0; i < 32; i++) sc += g_uf[h][i] * __half2float(szh[l * 32 + i]);
        sw[h][l] = (g_f[h][l] - 1.f) * __expf(sc - ESHIFT);   // same shift as mainloop
    }
    __syncthreads();
    {
        int h = tid >> 5, i = tid & 31;
        float d = 0.f;
#pragma unroll
        for (int l = 0; l < 64; l++) d += sw[h][l] * __half2float(szh[l * 32 + i]);
        red[4 + h * 32 + i] += d;
        if (tid < 4) {
            float ds = 0.f;
#pragma unroll
            for (int l = 0; l < 64; l++) ds += sw[tid][l];
            red[tid] += ds;
        }
    }
    __syncthreads();

    __shared__ float sout[32], szl[32], sq[32], su[4][32];
    if (tid < 32) {
        int h = tid >> 3;
        float inv = 1.f / red[h];
        float o = v_b[tid];
#pragma unroll
        for (int i = 0; i < 32; i++) o += v_w[tid * 32 + i] * (red[4 + h * 32 + i] * inv);
        sout[tid] = o;
    }
    __syncthreads();
    if (tid < 32) {
        float m = o_b[tid];
#pragma unroll
        for (int i = 0; i < 32; i++) m += sout[i] * o_w[tid * 32 + i];
        float zz = g_z[tid] + coupling[0] * m;
        float sp = (zz > 15.f) ? zz : log1pf(__expf(zz));
        szl[tid] = zz * tanhf(sp);
    }
    __syncthreads();
    if (tid < 32) {
        int p = tid & 1;
        float mn = 0.f;
#pragma unroll
        for (int d = 0; d < 16; d++) mn += szl[2 * d + p];
        mn *= (1.f / 16.f);
        float var = 0.f;
#pragma unroll
        for (int d = 0; d < 16; d++) { float dd = szl[2 * d + p] - mn; var += dd * dd; }
        var *= (1.f / 16.f);
        float zn = (szl[tid] - mn) * rsqrtf(var + 1e-5f) * norm_scale[0];
        g_z[tid] = zn;
        sout[tid] = zn;
        if (last) outp[tid] = zn;
    }
    __syncthreads();
    if (tid < 32) {
        float qq = q_b[tid];
#pragma unroll
        for (int i = 0; i < 32; i++) qq += sout[i] * q_w[tid * 32 + i];
        sq[tid] = 0.5f * qq;
    }
    __syncthreads();
    compute_u_f(sq, su, k_w, rbias, pos[0] - L + 64, tid, NTB);
    if (tid == 0) g_cnt = 0;
}

extern "C" void kernel_launch(void* const* d_in, const int* in_sizes, int n_in,
                              void* d_out, int out_size)
{
    const float* cand   = (const float*)d_in[0];
    const float* zp     = (const float*)d_in[1];
    const float* q_w    = (const float*)d_in[2];
    const float* q_b    = (const float*)d_in[3];
    const float* k_w    = (const float*)d_in[4];
    const float* v_w    = (const float*)d_in[6];
    const float* v_b    = (const float*)d_in[7];
    const float* o_w    = (const float*)d_in[8];
    const float* o_b    = (const float*)d_in[9];
    const float* rbias  = (const float*)d_in[10];
    const float* coup   = (const float*)d_in[11];
    const float* nscale = (const float*)d_in[12];
    const int*   pos    = (const int*)  d_in[13];

    int L = in_sizes[1] / 32;
    float* outp = (float*)d_out;

    k_convert<<<NBC, NTC>>>(zp, L, cand, q_w, q_b, k_w, rbias, pos);
    for (int s = 0; s < 8; s++)
        k_step<<<NBS, NTB>>>(L, k_w, v_w, v_b, o_w, o_b, q_w, q_b,
                             rbias, coup, nscale, pos, outp, s == 7);
}

// round 11
// speedup vs baseline: 2.0273x; 2.0273x over previous
#include <cuda_runtime.h>
#include <cuda_fp16.h>
#include <math.h>

#define LMAX 540672       // >= L + NBS*NTB/2 so unguarded prefetch is in-bounds
#define NBS  592          // step grid (4 blocks x 148 SMs, one wave)
#define NTB  128          // step block
#define NBC  592          // convert grid
#define NTC  256          // convert block
#define ESHIFT 6.0f
#define LG2E 1.44269504f

// fp16 copy of z_past: [L][32] halves (16B-aligned)
__device__ __align__(16) __half g_zh[(size_t)LMAX * 32];
// per-block partials: [block][132]  (c<4: s_h, c=4+h*32+i: S_h[i])
__device__ float  g_part[NBS * 132];
__device__ float  g_z[32];
__device__ float  g_uf[4][32];     // fp32 u (epilogue correction, natural scale)
__device__ __half2 g_uh[4][16];    // half2 u * log2(e) (mainloop scores)
__device__ float  g_f[4][64];      // correction factors for rows l<64
__device__ unsigned int g_cnt = 0;

// ---------------- scalar-only helpers (no address-taken arrays) ----------------
__device__ __forceinline__ __half2 u2h2(unsigned u) {
    __half2 h = *reinterpret_cast<__half2*>(&u); return h;
}
__device__ __forceinline__ unsigned h2u(__half2 h) {
    return *reinterpret_cast<unsigned*>(&h);
}
__device__ __forceinline__ __half2 h2shfl_xor(__half2 v, int o) {
    unsigned u = h2u(v);
    u = __shfl_xor_sync(0xffffffffu, u, o);
    return u2h2(u);
}
__device__ __forceinline__ __half2 h2ex2(__half2 x) {
    unsigned xi = h2u(x), ri;
    asm("ex2.approx.f16x2 %0,%1;" : "=r"(ri) : "r"(xi));
    return u2h2(ri);
}
__device__ __forceinline__ void ldg128(unsigned& a, unsigned& b, unsigned& c, unsigned& d,
                                       const void* p) {
    asm("ld.global.nc.v4.u32 {%0,%1,%2,%3},[%4];"
        : "=r"(a), "=r"(b), "=r"(c), "=r"(d) : "l"(p));
}

// ---- from smem sq (=0.5*q) compute u (g_uf natural, g_uh *log2e) and f (g_f)
__device__ __forceinline__ void compute_u_f(const float* sq, float (*su)[32],
                                            const float* k_w, const float* rbias,
                                            int off, int tid, int nthreads)
{
    if (tid < 128) {
        int h = tid >> 5, i = tid & 31;
        float u = 0.f;
#pragma unroll
        for (int j = 0; j < 8; j++) u += sq[8*h + j] * k_w[(8*h + j) * 32 + i];
        g_uf[h][i] = u;
        su[h][i] = u;
    }
    __syncthreads();
    if (tid < 64) {
        int h = tid >> 4, m = tid & 15;
        g_uh[h][m] = __floats2half2_rn(su[h][2*m] * LG2E, su[h][2*m+1] * LG2E);
    }
    for (int task = tid; task < 256; task += nthreads) {
        int h = task >> 6, l = task & 63;
        int idx = off + l;
        idx = idx < 0 ? 0 : (idx > 128 ? 128 : idx);
        float d = 0.f;
#pragma unroll
        for (int j = 0; j < 8; j++)
            d += sq[8*h + j] * (rbias[idx * 32 + 8*h + j] - rbias[128 * 32 + 8*h + j]);
        g_f[h][l] = __expf(d);
    }
}

// ---------------- convert: z_past -> fp16, plus step-0 init (block 0) -------
__global__ __launch_bounds__(NTC)
void k_convert(const float* __restrict__ zp, int L,
               const float* __restrict__ cand,
               const float* __restrict__ q_w, const float* __restrict__ q_b,
               const float* __restrict__ k_w, const float* __restrict__ rbias,
               const int* __restrict__ pos)
{
    if (blockIdx.x == 0) {
        __shared__ float scand[32], sq[32], su[4][32];
        int tid = threadIdx.x;
        if (tid < 32) { scand[tid] = cand[tid]; g_z[tid] = cand[tid]; }
        __syncthreads();
        if (tid < 32) {
            float qq = q_b[tid];
#pragma unroll
            for (int i = 0; i < 32; i++) qq += scand[i] * q_w[tid * 32 + i];
            sq[tid] = 0.5f * qq;
        }
        __syncthreads();
        compute_u_f(sq, su, k_w, rbias, pos[0] - L + 64, tid, NTC);
        __syncthreads();
    }
    const int stride = gridDim.x * blockDim.x;
    for (int l = blockIdx.x * blockDim.x + threadIdx.x; l < LMAX; l += stride) {
        int4 o0, o1, o2, o3;
        if (l < L) {
            const float4* row = (const float4*)(zp + (size_t)l * 32);
            float4 t0 = row[0], t1 = row[1], t2 = row[2], t3 = row[3];
            float4 t4 = row[4], t5 = row[5], t6 = row[6], t7 = row[7];
            o0.x = h2u(__floats2half2_rn(t0.x, t0.y)); o0.y = h2u(__floats2half2_rn(t0.z, t0.w));
            o0.z = h2u(__floats2half2_rn(t1.x, t1.y)); o0.w = h2u(__floats2half2_rn(t1.z, t1.w));
            o1.x = h2u(__floats2half2_rn(t2.x, t2.y)); o1.y = h2u(__floats2half2_rn(t2.z, t2.w));
            o1.z = h2u(__floats2half2_rn(t3.x, t3.y)); o1.w = h2u(__floats2half2_rn(t3.z, t3.w));
            o2.x = h2u(__floats2half2_rn(t4.x, t4.y)); o2.y = h2u(__floats2half2_rn(t4.z, t4.w));
            o2.z = h2u(__floats2half2_rn(t5.x, t5.y)); o2.w = h2u(__floats2half2_rn(t5.z, t5.w));
            o3.x = h2u(__floats2half2_rn(t6.x, t6.y)); o3.y = h2u(__floats2half2_rn(t6.z, t6.w));
            o3.z = h2u(__floats2half2_rn(t7.x, t7.y)); o3.w = h2u(__floats2half2_rn(t7.z, t7.w));
        } else {
            o0 = make_int4(0,0,0,0); o1 = o0; o2 = o0; o3 = o0;   // zero tail
        }
        int4* dst = (int4*)(g_zh + (size_t)l * 32);
        dst[0] = o0; dst[1] = o1; dst[2] = o2; dst[3] = o3;
    }
}

#define SCORE(zm, m) \
    p0 = __hfma2(zm, uh[0][m], p0); p1 = __hfma2(zm, uh[1][m], p1); \
    p2 = __hfma2(zm, uh[2][m], p2); p3 = __hfma2(zm, uh[3][m], p3);
#define ACCR(zm, m) \
    sacc[0][m] = __hfma2(e0, zm, sacc[0][m]); sacc[1][m] = __hfma2(e1, zm, sacc[1][m]); \
    sacc[2][m] = __hfma2(e2, zm, sacc[2][m]); sacc[3][m] = __hfma2(e3, zm, sacc[3][m]);

// ---------------- fused step: streaming + last-block epilogue ---------------
__global__ __launch_bounds__(NTB, 4)
void k_step(int L,
            const float* __restrict__ k_w,
            const float* __restrict__ v_w, const float* __restrict__ v_b,
            const float* __restrict__ o_w, const float* __restrict__ o_b,
            const float* __restrict__ q_w, const float* __restrict__ q_b,
            const float* __restrict__ rbias,
            const float* __restrict__ coupling,
            const float* __restrict__ norm_scale,
            const int* __restrict__ pos,
            float* __restrict__ outp, int last)
{
    const int tid  = threadIdx.x;
    const int gtid = blockIdx.x * NTB + tid;
    const int par  = gtid & 1;          // parity: which 16 components of the row
    const int lane = tid & 31;

    __half2 uh[4][8];
#pragma unroll
    for (int h = 0; h < 4; h++)
#pragma unroll
        for (int m = 0; m < 8; m++) uh[h][m] = g_uh[h][par * 8 + m];
    const __half2 bias = __floats2half2_rn(par ? 0.f : -ESHIFT * LG2E, 0.f);

    float s[4] = {0.f, 0.f, 0.f, 0.f};
    __half2 sacc[4][8];
#pragma unroll
    for (int h = 0; h < 4; h++)
#pragma unroll
        for (int m = 0; m < 8; m++) sacc[h][m] = __floats2half2_rn(0.f, 0.f);

    const int rs = (NBS * NTB) >> 1;
    int r = gtid >> 1;
    const char* base = (const char*)g_zh + par * 32;
    unsigned c0, c1, c2, c3, c4, c5, c6, c7;
    ldg128(c0, c1, c2, c3, base + (size_t)r * 64);
    ldg128(c4, c5, c6, c7, base + (size_t)r * 64 + 16);

    while (r < L) {
        int rn = r + rs;                      // unguarded: g_zh oversized
        unsigned n0, n1, n2, n3, n4, n5, n6, n7;
        ldg128(n0, n1, n2, n3, base + (size_t)rn * 64);
        ldg128(n4, n5, n6, n7, base + (size_t)rn * 64 + 16);

        __half2 z0 = u2h2(c0), z1 = u2h2(c1), z2 = u2h2(c2), z3 = u2h2(c3);
        __half2 z4 = u2h2(c4), z5 = u2h2(c5), z6 = u2h2(c6), z7 = u2h2(c7);

        __half2 p0 = __hfma2(z0, uh[0][0], bias);
        __half2 p1 = __hfma2(z0, uh[1][0], bias);
        __half2 p2 = __hfma2(z0, uh[2][0], bias);
        __half2 p3 = __hfma2(z0, uh[3][0], bias);
        SCORE(z1, 1) SCORE(z2, 2) SCORE(z3, 3)
        SCORE(z4, 4) SCORE(z5, 5) SCORE(z6, 6) SCORE(z7, 7)

        __half2 q01 = __hadd2(__lows2half2(p0, p1), __highs2half2(p0, p1));
        __half2 q23 = __hadd2(__lows2half2(p2, p3), __highs2half2(p2, p3));
        q01 = __hadd2(q01, h2shfl_xor(q01, 1));
        q23 = __hadd2(q23, h2shfl_xor(q23, 1));
        __half2 e01 = h2ex2(q01);             // exp(sc - ESHIFT) for heads 0,1
        __half2 e23 = h2ex2(q23);
        float2 f01 = __half22float2(e01), f23 = __half22float2(e23);
        s[0] += f01.x; s[1] += f01.y; s[2] += f23.x; s[3] += f23.y;

        __half2 e0 = __low2half2(e01), e1 = __high2half2(e01);
        __half2 e2 = __low2half2(e23), e3 = __high2half2(e23);
        ACCR(z0, 0) ACCR(z1, 1) ACCR(z2, 2) ACCR(z3, 3)
        ACCR(z4, 4) ACCR(z5, 5) ACCR(z6, 6) ACCR(z7, 7)

        c0 = n0; c1 = n1; c2 = n2; c3 = n3;
        c4 = n4; c5 = n5; c6 = n6; c7 = n7;
        r = rn;
    }

    // warp reduction among same-parity lanes (offsets 2,4,8,16)
#pragma unroll
    for (int o = 2; o <= 16; o <<= 1) {
#pragma unroll
        for (int h = 0; h < 4; h++) {
            s[h] += __shfl_xor_sync(0xffffffffu, s[h], o);
#pragma unroll
            for (int m = 0; m < 8; m++)
                sacc[h][m] = __hadd2(sacc[h][m], h2shfl_xor(sacc[h][m], o));
        }
    }

    __shared__ float sm_s[4][4];        // parity-0 only (parities are equal)
    __shared__ float sm_S[4][4][32];
    int w = tid >> 5;
    if (lane < 2) {
#pragma unroll
        for (int h = 0; h < 4; h++) {
            if (par == 0) sm_s[w][h] = s[h];
#pragma unroll
            for (int m = 0; m < 8; m++) {
                float2 f = __half22float2(sacc[h][m]);
                sm_S[w][h][par * 16 + 2*m]     = f.x;
                sm_S[w][h][par * 16 + 2*m + 1] = f.y;
            }
        }
    }
    __syncthreads();
    for (int c = tid; c < 132; c += NTB) {
        float r2;
        if (c < 4) {
            r2 = sm_s[0][c] + sm_s[1][c] + sm_s[2][c] + sm_s[3][c];
        } else {
            int h = (c - 4) >> 5, i = (c - 4) & 31;
            r2 = sm_S[0][h][i] + sm_S[1][h][i] + sm_S[2][h][i] + sm_S[3][h][i];
        }
        g_part[blockIdx.x * 132 + c] = r2;
    }

    // ---- last-block epilogue ----
    __shared__ bool amLast;
    __threadfence();
    if (tid == 0) {
        unsigned int v = atomicAdd(&g_cnt, 1u);
        amLast = (v == (unsigned int)(gridDim.x - 1));
    }
    __syncthreads();
    if (!amLast) return;

    __shared__ float red[132];
    {   // warp-parallel partial reduction (lane-strided, high MLP)
        for (int c = w; c < 132; c += 4) {
            float rr = 0.f;
            for (int b = lane; b < NBS; b += 32) rr += g_part[b * 132 + c];
#pragma unroll
            for (int o = 16; o; o >>= 1) rr += __shfl_down_sync(0xffffffffu, rr, o);
            if (lane == 0) red[c] = rr;
        }
    }
    // first 64 rows of z (rel-bias correction region)
    __shared__ __align__(16) __half szh[64 * 32];
    for (int t = tid; t < 256; t += NTB)
        ((int4*)szh)[t] = ((const int4*)g_zh)[t];
    __shared__ float sw[4][64];
    __syncthreads();

    for (int task = tid; task < 256; task += NTB) {
        int h = task >> 6, l = task & 63;
        float sc = 0.f;
#pragma unroll
        for (int i = 0; i < 32; i++) sc += g_uf[h][i] * __half2float(szh[l * 32 + i]);
        sw[h][l] = (g_f[h][l] - 1.f) * __expf(sc - ESHIFT);   // same shift as mainloop
    }
    __syncthreads();
    {
        int h = tid >> 5, i = tid & 31;
        float d = 0.f;
#pragma unroll
        for (int l = 0; l < 64; l++) d += sw[h][l] * __half2float(szh[l * 32 + i]);
        red[4 + h * 32 + i] += d;
        if (tid < 4) {
            float ds = 0.f;
#pragma unroll
            for (int l = 0; l < 64; l++) ds += sw[tid][l];
            red[tid] += ds;
        }
    }
    __syncthreads();

    __shared__ float sout[32], szl[32], sq[32], su[4][32];
    if (tid < 32) {
        int h = tid >> 3;
        float inv = 1.f / red[h];
        float o = v_b[tid];
#pragma unroll
        for (int i = 0; i < 32; i++) o += v_w[tid * 32 + i] * (red[4 + h * 32 + i] * inv);
        sout[tid] = o;
    }
    __syncthreads();
    if (tid < 32) {
        float m = o_b[tid];
#pragma unroll
        for (int i = 0; i < 32; i++) m += sout[i] * o_w[tid * 32 + i];
        float zz = g_z[tid] + coupling[0] * m;
        float sp = (zz > 15.f) ? zz : log1pf(__expf(zz));
        szl[tid] = zz * tanhf(sp);
    }
    __syncthreads();
    if (tid < 32) {
        int p = tid & 1;
        float mn = 0.f;
#pragma unroll
        for (int d = 0; d < 16; d++) mn += szl[2 * d + p];
        mn *= (1.f / 16.f);
        float var = 0.f;
#pragma unroll
        for (int d = 0; d < 16; d++) { float dd = szl[2 * d + p] - mn; var += dd * dd; }
        var *= (1.f / 16.f);
        float zn = (szl[tid] - mn) * rsqrtf(var + 1e-5f) * norm_scale[0];
        g_z[tid] = zn;
        sout[tid] = zn;
        if (last) outp[tid] = zn;
    }
    __syncthreads();
    if (tid < 32) {
        float qq = q_b[tid];
#pragma unroll
        for (int i = 0; i < 32; i++) qq += sout[i] * q_w[tid * 32 + i];
        sq[tid] = 0.5f * qq;
    }
    __syncthreads();
    compute_u_f(sq, su, k_w, rbias, pos[0] - L + 64, tid, NTB);
    if (tid == 0) g_cnt = 0;
}

extern "C" void kernel_launch(void* const* d_in, const int* in_sizes, int n_in,
                              void* d_out, int out_size)
{
    const float* cand   = (const float*)d_in[0];
    const float* zp     = (const float*)d_in[1];
    const float* q_w    = (const float*)d_in[2];
    const float* q_b    = (const float*)d_in[3];
    const float* k_w    = (const float*)d_in[4];
    const float* v_w    = (const float*)d_in[6];
    const float* v_b    = (const float*)d_in[7];
    const float* o_w    = (const float*)d_in[8];
    const float* o_b    = (const float*)d_in[9];
    const float* rbias  = (const float*)d_in[10];
    const float* coup   = (const float*)d_in[11];
    const float* nscale = (const float*)d_in[12];
    const int*   pos    = (const int*)  d_in[13];

    int L = in_sizes[1] / 32;
    float* outp = (float*)d_out;

    k_convert<<<NBC, NTC>>>(zp, L, cand, q_w, q_b, k_w, rbias, pos);
    for (int s = 0; s < 8; s++)
        k_step<<<NBS, NTB>>>(L, k_w, v_w, v_b, o_w, o_b, q_w, q_b,
                             rbias, coup, nscale, pos, outp, s == 7);
}

// round 12
// speedup vs baseline: 2.7507x; 1.3568x over previous
#include <cuda_runtime.h>
#include <cuda_fp16.h>
#include <math.h>

#define LMAX 540672       // >= L + NBS*NTB/4 so unguarded prefetch is in-bounds
#define NBS  444          // step grid (3 blocks x 148 SMs, one wave)
#define NTB  256          // step block
#define NBC  592          // convert grid
#define NTC  256          // convert block
#define ESHIFT 6.0f
#define LG2E 1.44269504f

// fp16 copy of z_past: [L][32] halves (16B-aligned)
__device__ __align__(16) __half g_zh[(size_t)LMAX * 32];
// per-block partials: [block][132]  (c<4: s_h, c=4+h*32+i: S_h[i])
__device__ float  g_part[NBS * 132];
__device__ float  g_z[32];
__device__ float  g_uf[4][32];     // fp32 u (epilogue correction, natural scale)
__device__ __half2 g_uh[4][16];    // half2 u * log2(e) (mainloop scores)
__device__ float  g_f[4][64];      // correction factors for rows l<64
__device__ unsigned int g_cnt = 0;

// ---------------- scalar-only helpers (no address-taken arrays) -------------
__device__ __forceinline__ __half2 u2h2(unsigned u) {
    __half2 h = *reinterpret_cast<__half2*>(&u); return h;
}
__device__ __forceinline__ unsigned h2u(__half2 h) {
    return *reinterpret_cast<unsigned*>(&h);
}
__device__ __forceinline__ __half2 h2shfl_xor(__half2 v, int o) {
    unsigned u = h2u(v);
    u = __shfl_xor_sync(0xffffffffu, u, o);
    return u2h2(u);
}
__device__ __forceinline__ __half2 h2ex2(__half2 x) {
    unsigned xi = h2u(x), ri;
    asm("ex2.approx.f16x2 %0,%1;" : "=r"(ri) : "r"(xi));
    return u2h2(ri);
}
__device__ __forceinline__ void ldg128(unsigned& a, unsigned& b, unsigned& c, unsigned& d,
                                       const void* p) {
    asm("ld.global.nc.v4.u32 {%0,%1,%2,%3},[%4];"
        : "=r"(a), "=r"(b), "=r"(c), "=r"(d) : "l"(p));
}

// ---- from smem sq (=0.5*q) compute u (g_uf natural, g_uh *log2e) and f (g_f)
__device__ __forceinline__ void compute_u_f(const float* sq, float (*su)[32],
                                            const float* k_w, const float* rbias,
                                            int off, int tid, int nthreads)
{
    if (tid < 128) {
        int h = tid >> 5, i = tid & 31;
        float u = 0.f;
#pragma unroll
        for (int j = 0; j < 8; j++) u += sq[8*h + j] * k_w[(8*h + j) * 32 + i];
        g_uf[h][i] = u;
        su[h][i] = u;
    }
    __syncthreads();
    if (tid < 64) {
        int h = tid >> 4, m = tid & 15;
        g_uh[h][m] = __floats2half2_rn(su[h][2*m] * LG2E, su[h][2*m+1] * LG2E);
    }
    for (int task = tid; task < 256; task += nthreads) {
        int h = task >> 6, l = task & 63;
        int idx = off + l;
        idx = idx < 0 ? 0 : (idx > 128 ? 128 : idx);
        float d = 0.f;
#pragma unroll
        for (int j = 0; j < 8; j++)
            d += sq[8*h + j] * (rbias[idx * 32 + 8*h + j] - rbias[128 * 32 + 8*h + j]);
        g_f[h][l] = __expf(d);
    }
}

// ---------------- convert: z_past -> fp16, plus step-0 init (block 0) -------
__global__ __launch_bounds__(NTC)
void k_convert(const float* __restrict__ zp, int L,
               const float* __restrict__ cand,
               const float* __restrict__ q_w, const float* __restrict__ q_b,
               const float* __restrict__ k_w, const float* __restrict__ rbias,
               const int* __restrict__ pos)
{
    if (blockIdx.x == 0) {
        __shared__ float scand[32], sq[32], su[4][32];
        int tid = threadIdx.x;
        if (tid < 32) { scand[tid] = cand[tid]; g_z[tid] = cand[tid]; }
        __syncthreads();
        if (tid < 32) {
            float qq = q_b[tid];
#pragma unroll
            for (int i = 0; i < 32; i++) qq += scand[i] * q_w[tid * 32 + i];
            sq[tid] = 0.5f * qq;
        }
        __syncthreads();
        compute_u_f(sq, su, k_w, rbias, pos[0] - L + 64, tid, NTC);
        __syncthreads();
    }
    const int stride = gridDim.x * blockDim.x;
    for (int l = blockIdx.x * blockDim.x + threadIdx.x; l < LMAX; l += stride) {
        int4 o0, o1, o2, o3;
        if (l < L) {
            const float4* row = (const float4*)(zp + (size_t)l * 32);
            float4 t0 = row[0], t1 = row[1], t2 = row[2], t3 = row[3];
            float4 t4 = row[4], t5 = row[5], t6 = row[6], t7 = row[7];
            o0.x = h2u(__floats2half2_rn(t0.x, t0.y)); o0.y = h2u(__floats2half2_rn(t0.z, t0.w));
            o0.z = h2u(__floats2half2_rn(t1.x, t1.y)); o0.w = h2u(__floats2half2_rn(t1.z, t1.w));
            o1.x = h2u(__floats2half2_rn(t2.x, t2.y)); o1.y = h2u(__floats2half2_rn(t2.z, t2.w));
            o1.z = h2u(__floats2half2_rn(t3.x, t3.y)); o1.w = h2u(__floats2half2_rn(t3.z, t3.w));
            o2.x = h2u(__floats2half2_rn(t4.x, t4.y)); o2.y = h2u(__floats2half2_rn(t4.z, t4.w));
            o2.z = h2u(__floats2half2_rn(t5.x, t5.y)); o2.w = h2u(__floats2half2_rn(t5.z, t5.w));
            o3.x = h2u(__floats2half2_rn(t6.x, t6.y)); o3.y = h2u(__floats2half2_rn(t6.z, t6.w));
            o3.z = h2u(__floats2half2_rn(t7.x, t7.y)); o3.w = h2u(__floats2half2_rn(t7.z, t7.w));
        } else {
            o0 = make_int4(0,0,0,0); o1 = o0; o2 = o0; o3 = o0;   // zero tail
        }
        int4* dst = (int4*)(g_zh + (size_t)l * 32);
        dst[0] = o0; dst[1] = o1; dst[2] = o2; dst[3] = o3;
    }
}

// ---------------- fused step: quad-per-row streaming + last-block epilogue --
__global__ __launch_bounds__(NTB, 3)
void k_step(int L,
            const float* __restrict__ k_w,
            const float* __restrict__ v_w, const float* __restrict__ v_b,
            const float* __restrict__ o_w, const float* __restrict__ o_b,
            const float* __restrict__ q_w, const float* __restrict__ q_b,
            const float* __restrict__ rbias,
            const float* __restrict__ coupling,
            const float* __restrict__ norm_scale,
            const int* __restrict__ pos,
            float* __restrict__ outp, int last)
{
    const int tid  = threadIdx.x;
    const int gtid = blockIdx.x * NTB + tid;
    const int qg   = gtid & 3;          // quad lane -> component group [8q..8q+8)
    const int lane = tid & 31;
    const int w    = tid >> 5;

    __half2 uh0[4], uh1[4], uh2[4], uh3[4];
#pragma unroll
    for (int m = 0; m < 4; m++) {
        uh0[m] = g_uh[0][qg * 4 + m];
        uh1[m] = g_uh[1][qg * 4 + m];
        uh2[m] = g_uh[2][qg * 4 + m];
        uh3[m] = g_uh[3][qg * 4 + m];
    }
    const __half2 ebias = __float2half2_rn(-ESHIFT * LG2E);

    float s0 = 0.f, s1 = 0.f, s2 = 0.f, s3 = 0.f;
    __half2 a0[4], a1[4], a2[4], a3[4];
#pragma unroll
    for (int m = 0; m < 4; m++) {
        a0[m] = __floats2half2_rn(0.f, 0.f); a1[m] = a0[m];
        a2[m] = a0[m]; a3[m] = a0[m];
    }

    const int rs = (NBS * NTB) >> 2;
    int r = gtid >> 2;
    const char* base = (const char*)g_zh + qg * 16;
    unsigned c0, c1, c2, c3;
    ldg128(c0, c1, c2, c3, base + (size_t)r * 64);

    while (r < L) {
        int rn = r + rs;                      // unguarded: g_zh oversized, tail zero
        unsigned n0, n1, n2, n3;
        ldg128(n0, n1, n2, n3, base + (size_t)rn * 64);

        __half2 z0 = u2h2(c0), z1 = u2h2(c1), z2 = u2h2(c2), z3 = u2h2(c3);

        __half2 p0 = __hmul2(z0, uh0[0]);
        __half2 p1 = __hmul2(z0, uh1[0]);
        __half2 p2 = __hmul2(z0, uh2[0]);
        __half2 p3 = __hmul2(z0, uh3[0]);
        p0 = __hfma2(z1, uh0[1], p0); p1 = __hfma2(z1, uh1[1], p1);
        p2 = __hfma2(z1, uh2[1], p2); p3 = __hfma2(z1, uh3[1], p3);
        p0 = __hfma2(z2, uh0[2], p0); p1 = __hfma2(z2, uh1[2], p1);
        p2 = __hfma2(z2, uh2[2], p2); p3 = __hfma2(z2, uh3[2], p3);
        p0 = __hfma2(z3, uh0[3], p0); p1 = __hfma2(z3, uh1[3], p1);
        p2 = __hfma2(z3, uh2[3], p2); p3 = __hfma2(z3, uh3[3], p3);

        __half2 q01 = __hadd2(__lows2half2(p0, p1), __highs2half2(p0, p1));
        __half2 q23 = __hadd2(__lows2half2(p2, p3), __highs2half2(p2, p3));
        q01 = __hadd2(q01, h2shfl_xor(q01, 1));
        q23 = __hadd2(q23, h2shfl_xor(q23, 1));
        q01 = __hadd2(q01, h2shfl_xor(q01, 2));
        q23 = __hadd2(q23, h2shfl_xor(q23, 2));
        q01 = __hadd2(q01, ebias);
        q23 = __hadd2(q23, ebias);
        __half2 e01 = h2ex2(q01);             // exp(sc - ESHIFT) heads 0,1
        __half2 e23 = h2ex2(q23);
        float2 f01 = __half22float2(e01), f23 = __half22float2(e23);
        s0 += f01.x; s1 += f01.y; s2 += f23.x; s3 += f23.y;

        __half2 e0 = __low2half2(e01), e1 = __high2half2(e01);
        __half2 e2 = __low2half2(e23), e3 = __high2half2(e23);
#pragma unroll
        for (int m = 0; m < 4; m++) {
            __half2 zm = (m == 0) ? z0 : (m == 1) ? z1 : (m == 2) ? z2 : z3;
            a0[m] = __hfma2(e0, zm, a0[m]);
            a1[m] = __hfma2(e1, zm, a1[m]);
            a2[m] = __hfma2(e2, zm, a2[m]);
            a3[m] = __hfma2(e3, zm, a3[m]);
        }
        c0 = n0; c1 = n1; c2 = n2; c3 = n3;
        r = rn;
    }

    // warp reduction over quads (offsets 4,8,16); lane q keeps group q
#pragma unroll
    for (int o = 4; o <= 16; o <<= 1) {
        s0 += __shfl_xor_sync(0xffffffffu, s0, o);
        s1 += __shfl_xor_sync(0xffffffffu, s1, o);
        s2 += __shfl_xor_sync(0xffffffffu, s2, o);
        s3 += __shfl_xor_sync(0xffffffffu, s3, o);
#pragma unroll
        for (int m = 0; m < 4; m++) {
            a0[m] = __hadd2(a0[m], h2shfl_xor(a0[m], o));
            a1[m] = __hadd2(a1[m], h2shfl_xor(a1[m], o));
            a2[m] = __hadd2(a2[m], h2shfl_xor(a2[m], o));
            a3[m] = __hadd2(a3[m], h2shfl_xor(a3[m], o));
        }
    }

    __shared__ float sm_s[NTB / 32][4];
    __shared__ float sm_S[NTB / 32][4][32];
    if (lane < 4) {
#pragma unroll
        for (int m = 0; m < 4; m++) {
            float2 f;
            f = __half22float2(a0[m]);
            sm_S[w][0][qg * 8 + 2*m] = f.x; sm_S[w][0][qg * 8 + 2*m + 1] = f.y;
            f = __half22float2(a1[m]);
            sm_S[w][1][qg * 8 + 2*m] = f.x; sm_S[w][1][qg * 8 + 2*m + 1] = f.y;
            f = __half22float2(a2[m]);
            sm_S[w][2][qg * 8 + 2*m] = f.x; sm_S[w][2][qg * 8 + 2*m + 1] = f.y;
            f = __half22float2(a3[m]);
            sm_S[w][3][qg * 8 + 2*m] = f.x; sm_S[w][3][qg * 8 + 2*m + 1] = f.y;
        }
        if (lane == 0) {
            sm_s[w][0] = s0; sm_s[w][1] = s1; sm_s[w][2] = s2; sm_s[w][3] = s3;
        }
    }
    __syncthreads();
    for (int c = tid; c < 132; c += NTB) {
        float r2 = 0.f;
        if (c < 4) {
#pragma unroll
            for (int ww = 0; ww < NTB / 32; ww++) r2 += sm_s[ww][c];
        } else {
            int h = (c - 4) >> 5, i = (c - 4) & 31;
#pragma unroll
            for (int ww = 0; ww < NTB / 32; ww++) r2 += sm_S[ww][h][i];
        }
        g_part[blockIdx.x * 132 + c] = r2;
    }

    // ---- last-block epilogue ----
    __shared__ bool amLast;
    __threadfence();
    if (tid == 0) {
        unsigned int v = atomicAdd(&g_cnt, 1u);
        amLast = (v == (unsigned int)(gridDim.x - 1));
    }
    __syncthreads();
    if (!amLast) return;

    __shared__ float red[132];
    {   // warp-parallel partial reduction (lane-strided, high MLP)
        for (int c = w; c < 132; c += NTB / 32) {
            float rr = 0.f;
            for (int b = lane; b < NBS; b += 32) rr += g_part[b * 132 + c];
#pragma unroll
            for (int o = 16; o; o >>= 1) rr += __shfl_down_sync(0xffffffffu, rr, o);
            if (lane == 0) red[c] = rr;
        }
    }
    // first 64 rows of z (rel-bias correction region)
    __shared__ __align__(16) __half szh[64 * 32];
    for (int t = tid; t < 256; t += NTB)
        ((int4*)szh)[t] = ((const int4*)g_zh)[t];
    __shared__ float sw[4][64];
    __syncthreads();

    for (int task = tid; task < 256; task += NTB) {
        int h = task >> 6, l = task & 63;
        float sc = 0.f;
#pragma unroll
        for (int i = 0; i < 32; i++) sc += g_uf[h][i] * __half2float(szh[l * 32 + i]);
        sw[h][l] = (g_f[h][l] - 1.f) * __expf(sc - ESHIFT);   // same shift as mainloop
    }
    __syncthreads();
    if (tid < 128) {
        int h = tid >> 5, i = tid & 31;
        float d = 0.f;
#pragma unroll
        for (int l = 0; l < 64; l++) d += sw[h][l] * __half2float(szh[l * 32 + i]);
        red[4 + h * 32 + i] += d;
        if (tid < 4) {
            float ds = 0.f;
#pragma unroll
            for (int l = 0; l < 64; l++) ds += sw[tid][l];
            red[tid] += ds;
        }
    }
    __syncthreads();

    __shared__ float sout[32], szl[32], sq[32], su[4][32];
    if (tid < 32) {
        int h = tid >> 3;
        float inv = 1.f / red[h];
        float o = v_b[tid];
#pragma unroll
        for (int i = 0; i < 32; i++) o += v_w[tid * 32 + i] * (red[4 + h * 32 + i] * inv);
        sout[tid] = o;
    }
    __syncthreads();
    if (tid < 32) {
        float m = o_b[tid];
#pragma unroll
        for (int i = 0; i < 32; i++) m += sout[i] * o_w[tid * 32 + i];
        float zz = g_z[tid] + coupling[0] * m;
        float sp = (zz > 15.f) ? zz : log1pf(__expf(zz));
        szl[tid] = zz * tanhf(sp);
    }
    __syncthreads();
    if (tid < 32) {
        int p = tid & 1;
        float mn = 0.f;
#pragma unroll
        for (int d = 0; d < 16; d++) mn += szl[2 * d + p];
        mn *= (1.f / 16.f);
        float var = 0.f;
#pragma unroll
        for (int d = 0; d < 16; d++) { float dd = szl[2 * d + p] - mn; var += dd * dd; }
        var *= (1.f / 16.f);
        float zn = (szl[tid] - mn) * rsqrtf(var + 1e-5f) * norm_scale[0];
        g_z[tid] = zn;
        sout[tid] = zn;
        if (last) outp[tid] = zn;
    }
    __syncthreads();
    if (tid < 32) {
        float qq = q_b[tid];
#pragma unroll
        for (int i = 0; i < 32; i++) qq += sout[i] * q_w[tid * 32 + i];
        sq[tid] = 0.5f * qq;
    }
    __syncthreads();
    compute_u_f(sq, su, k_w, rbias, pos[0] - L + 64, tid, NTB);
    if (tid == 0) g_cnt = 0;
}

extern "C" void kernel_launch(void* const* d_in, const int* in_sizes, int n_in,
                              void* d_out, int out_size)
{
    const float* cand   = (const float*)d_in[0];
    const float* zp     = (const float*)d_in[1];
    const float* q_w    = (const float*)d_in[2];
    const float* q_b    = (const float*)d_in[3];
    const float* k_w    = (const float*)d_in[4];
    const float* v_w    = (const float*)d_in[6];
    const float* v_b    = (const float*)d_in[7];
    const float* o_w    = (const float*)d_in[8];
    const float* o_b    = (const float*)d_in[9];
    const float* rbias  = (const float*)d_in[10];
    const float* coup   = (const float*)d_in[11];
    const float* nscale = (const float*)d_in[12];
    const int*   pos    = (const int*)  d_in[13];

    int L = in_sizes[1] / 32;
    float* outp = (float*)d_out;

    k_convert<<<NBC, NTC>>>(zp, L, cand, q_w, q_b, k_w, rbias, pos);
    for (int s = 0; s < 8; s++)
        k_step<<<NBS, NTB>>>(L, k_w, v_w, v_b, o_w, o_b, q_w, q_b,
                             rbias, coup, nscale, pos, outp, s == 7);
}